// round 6
// baseline (speedup 1.0000x reference)
#include <cuda_runtime.h>

#define B_ 8192
#define S_ 4096
#define TPB 256
#define CHUNK 16           // S_ / TPB
#define EPS_ 1e-8f
#define LNEPS_ 1e-5f

// scratch for per-row features (B_ x 4) — __device__ global, no allocation
__device__ float g_combined[B_ * 4];

__device__ __forceinline__ int padi(int i) { return i + (i >> 4); }  // stride-17, bank-conflict-free

// ---------------------------------------------------------------------------
// Kernel A: per-row feature extraction (HBM-bound streaming)
// ---------------------------------------------------------------------------
__global__ void __launch_bounds__(TPB) feat_kernel(const float* __restrict__ prices)
{
    __shared__ float sI[S_ + (S_ >> 4)];   // padded inclusive prefix sums
    __shared__ float s_scan[16];
    __shared__ float s_red[16];
    __shared__ float s_plast, s_pm10;

    const int b    = blockIdx.x;
    const int t    = threadIdx.x;
    const int lane = t & 31;
    const int wid  = t >> 5;

    const float4* row4 =
        reinterpret_cast<const float4*>(prices + (size_t)b * S_) + t * (CHUNK / 4);

    // load 16 contiguous floats
    float p[CHUNK];
#pragma unroll
    for (int q = 0; q < CHUNK / 4; q++) {
        float4 v = row4[q];
        p[q * 4 + 0] = v.x; p[q * 4 + 1] = v.y;
        p[q * 4 + 2] = v.z; p[q * 4 + 3] = v.w;
    }

    // local inclusive scan + sum of squares
    float c[CHUNK];
    float p2 = p[0] * p[0];
    c[0] = p[0];
#pragma unroll
    for (int k = 1; k < CHUNK; k++) {
        c[k] = c[k - 1] + p[k];
        p2   = fmaf(p[k], p[k], p2);
    }
    const float tot = c[CHUNK - 1];

    // block-wide exclusive scan of per-thread totals (warp shuffles)
    float v = tot;
#pragma unroll
    for (int off = 1; off < 32; off <<= 1) {
        float n = __shfl_up_sync(0xffffffffu, v, off);
        if (lane >= off) v += n;
    }
    if (lane == 31) s_scan[wid] = v;
    if (t == TPB - 1) { s_plast = p[CHUNK - 1]; s_pm10 = p[CHUNK - 10]; } // i=4095, i=4086
    __syncthreads();
    if (wid == 0) {
        float w = (lane < 8) ? s_scan[lane] : 0.f;
#pragma unroll
        for (int off = 1; off < 8; off <<= 1) {
            float n = __shfl_up_sync(0xffffffffu, w, off);
            if (lane >= off) w += n;
        }
        if (lane < 8) s_scan[8 + lane] = w;
    }
    __syncthreads();
    const float base = ((wid > 0) ? s_scan[8 + wid - 1] : 0.f) + (v - tot);

    // write inclusive prefix (padded) to smem
#pragma unroll
    for (int k = 0; k < CHUNK; k++) sI[padi(t * CHUNK + k)] = base + c[k];
    __syncthreads();

    // trend: (p - sma20)/(sma20 + eps); sma20 = (I[i] - I[i-20]) / min(i+1,20)
    float tsum = 0.f;
    if (t >= 2) {
        // all i >= 32: full 20-window, rcnt = 0.05 (common path: 1 MUFU/elem)
#pragma unroll
        for (int k = 0; k < CHUNK; k++) {
            int   i  = t * CHUNK + k;
            float I  = base + c[k];
            float Ip = sI[padi(i - 20)];
            float sma = (I - Ip) * 0.05f;
            tsum += __fdividef(p[k] - sma, sma + EPS_);
        }
    } else {
        // threads 0,1 handle the clamped-window start
#pragma unroll
        for (int k = 0; k < CHUNK; k++) {
            int   i  = t * CHUNK + k;
            float I  = base + c[k];
            float Ip = (i >= 20) ? sI[padi(i - 20)] : 0.f;
            float cnt = (i >= 20) ? 20.f : (float)(i + 1);
            float sma = __fdividef(I - Ip, cnt);
            tsum += __fdividef(p[k] - sma, sma + EPS_);
        }
    }

    // block reduce tsum, p2
#pragma unroll
    for (int off = 16; off > 0; off >>= 1) {
        tsum += __shfl_xor_sync(0xffffffffu, tsum, off);
        p2   += __shfl_xor_sync(0xffffffffu, p2,   off);
    }
    if (lane == 0) { s_red[wid] = tsum; s_red[8 + wid] = p2; }
    __syncthreads();

    if (t == 0) {
        float T = 0.f, P2 = 0.f;
#pragma unroll
        for (int i = 0; i < 8; i++) { T += s_red[i]; P2 += s_red[8 + i]; }
        float psum  = sI[padi(S_ - 1)];
        float mean  = psum * (1.0f / S_);
        float f_trend = T * (1.0f / S_);
        float pl = s_plast, pm10 = s_pm10;
        float f_mom = (pl - pm10) / (pm10 + EPS_);
        float f_mr  = (pl - mean) / (mean + EPS_);
        float var   = (P2 - (float)S_ * mean * mean) * (1.0f / (float)(S_ - 1));
        float f_cyc = sqrtf(fmaxf(var, 0.f)) / (mean + EPS_);
        float4 cmb  = make_float4(f_trend, f_mom, f_mr, f_cyc);
        *reinterpret_cast<float4*>(&g_combined[b * 4]) = cmb;
    }
}

// ---------------------------------------------------------------------------
// Kernel B: encoders + LN + MLP head + softmax.  head_w1 lives in registers.
// ---------------------------------------------------------------------------
#define MLP_BLOCKS 512

__global__ void __launch_bounds__(TPB) mlp_kernel(
    const float* __restrict__ enc_w,  const float* __restrict__ enc_b,
    const float* __restrict__ enc_g,  const float* __restrict__ enc_beta,
    const float* __restrict__ W1,     const float* __restrict__ b1,
    const float* __restrict__ W2,     const float* __restrict__ b2,
    float* __restrict__ rf_out, float* __restrict__ probs_out)
{
    __shared__ float s_rf[256];
    __shared__ float s_part[256];
    __shared__ float s_h[64];
    __shared__ float s_logit[4];
    __shared__ float s_wsum[8], s_wsq[8];
    __shared__ float s_b1[64], s_W2[256], s_b2[4];

    const int t    = threadIdx.x;
    const int lane = t & 31, wid = t >> 5;
    const int q = t >> 6;   // encoder index e / quarter of head_w1 rows
    const int k = t & 63;   // output column within 64

    // head_w1 slice in registers: w[jj] = W1[(q*64+jj)][k]
    float w[64];
#pragma unroll
    for (int jj = 0; jj < 64; jj++) w[jj] = W1[(q * 64 + jj) * 64 + k];

    const float ew0 = enc_w[q * 256 + 0 * 64 + k];
    const float ew1 = enc_w[q * 256 + 1 * 64 + k];
    const float ew2 = enc_w[q * 256 + 2 * 64 + k];
    const float ew3 = enc_w[q * 256 + 3 * 64 + k];
    const float eb  = enc_b[q * 64 + k];
    const float gg  = enc_g[q * 64 + k];
    const float bb  = enc_beta[q * 64 + k];

    if (t < 64) s_b1[t] = b1[t];
    s_W2[t] = W2[t];
    if (t < 4) s_b2[t] = b2[t];
    __syncthreads();

    for (int r = blockIdx.x; r < B_; r += gridDim.x) {
        const float4 cb = *reinterpret_cast<const float4*>(&g_combined[r * 4]);

        // encoder: pre-activation, relu
        float pre = eb;
        pre = fmaf(ew0, cb.x, pre);
        pre = fmaf(ew1, cb.y, pre);
        pre = fmaf(ew2, cb.z, pre);
        pre = fmaf(ew3, cb.w, pre);
        float x = fmaxf(pre, 0.f);

        // layernorm over each 64-group (2 warps per group)
        float s = x, s2 = x * x;
#pragma unroll
        for (int off = 16; off > 0; off >>= 1) {
            s  += __shfl_xor_sync(0xffffffffu, s,  off);
            s2 += __shfl_xor_sync(0xffffffffu, s2, off);
        }
        if (lane == 0) { s_wsum[wid] = s; s_wsq[wid] = s2; }
        __syncthreads();
        const int gw = q * 2;
        float gs   = s_wsum[gw] + s_wsum[gw + 1];
        float gs2  = s_wsq[gw]  + s_wsq[gw + 1];
        float mu   = gs * (1.f / 64.f);
        float varr = gs2 * (1.f / 64.f) - mu * mu;
        float y = (x - mu) * rsqrtf(varr + LNEPS_) * gg + bb;
        s_rf[t] = y;
        rf_out[(size_t)r * 256 + t] = y;
        __syncthreads();

        // h = relu(rf @ W1 + b1): each thread does a 64-length partial for column k
        float part = 0.f;
        const float4* rf4 = reinterpret_cast<const float4*>(&s_rf[q * 64]);
#pragma unroll
        for (int jj = 0; jj < 16; jj++) {
            float4 rv = rf4[jj];
            part = fmaf(w[jj * 4 + 0], rv.x, part);
            part = fmaf(w[jj * 4 + 1], rv.y, part);
            part = fmaf(w[jj * 4 + 2], rv.z, part);
            part = fmaf(w[jj * 4 + 3], rv.w, part);
        }
        s_part[t] = part;
        __syncthreads();

        if (t < 64) {
            float h = s_b1[t] + s_part[t] + s_part[64 + t] + s_part[128 + t] + s_part[192 + t];
            s_h[t] = fmaxf(h, 0.f);
        }
        __syncthreads();

        if (t < 4) {
            float l = s_b2[t];
#pragma unroll
            for (int kk = 0; kk < 64; kk++) l = fmaf(s_h[kk], s_W2[kk * 4 + t], l);
            s_logit[t] = l;
        }
        __syncthreads();

        if (t < 4) {
            float m  = fmaxf(fmaxf(s_logit[0], s_logit[1]), fmaxf(s_logit[2], s_logit[3]));
            float e0 = __expf(s_logit[0] - m), e1 = __expf(s_logit[1] - m);
            float e2 = __expf(s_logit[2] - m), e3 = __expf(s_logit[3] - m);
            float den  = e0 + e1 + e2 + e3;
            float mine = (t == 0) ? e0 : (t == 1) ? e1 : (t == 2) ? e2 : e3;
            probs_out[(size_t)r * 4 + t] = __fdividef(mine, den);
        }
        __syncthreads();   // protect smem reuse across row iterations
    }
}

// ---------------------------------------------------------------------------
extern "C" void kernel_launch(void* const* d_in, const int* in_sizes, int n_in,
                              void* d_out, int out_size)
{
    const float* prices   = (const float*)d_in[0];  // (8192, 4096, 1)
    const float* enc_w    = (const float*)d_in[1];  // (4, 4, 64)
    const float* enc_b    = (const float*)d_in[2];  // (4, 64)
    const float* enc_g    = (const float*)d_in[3];  // (4, 64)
    const float* enc_beta = (const float*)d_in[4];  // (4, 64)
    const float* head_w1  = (const float*)d_in[5];  // (256, 64)
    const float* head_b1  = (const float*)d_in[6];  // (64,)
    const float* head_w2  = (const float*)d_in[7];  // (64, 4)
    const float* head_b2  = (const float*)d_in[8];  // (4,)

    float* out      = (float*)d_out;
    float* rf_out   = out;                      // 8192*256
    float* probs_out = out + (size_t)B_ * 256;  // 8192*4

    feat_kernel<<<B_, TPB>>>(prices);
    mlp_kernel<<<MLP_BLOCKS, TPB>>>(enc_w, enc_b, enc_g, enc_beta,
                                    head_w1, head_b1, head_w2, head_b2,
                                    rf_out, probs_out);
}

// round 8
// speedup vs baseline: 1.4298x; 1.4298x over previous
#include <cuda_runtime.h>

#define B_ 8192
#define S_ 4096
#define TPB 256
#define CHUNK 16           // S_ / TPB
#define EPS_ 1e-8f
#define LNEPS_ 1e-5f

// scratch for per-row features (B_ x 4) — __device__ global, no allocation
__device__ float g_combined[B_ * 4];

__device__ __forceinline__ int padi(int i) { return i + (i >> 4); }  // stride-17, bank-conflict-free

// ---------------------------------------------------------------------------
// Kernel A: per-row feature extraction (HBM-bound streaming)
// ---------------------------------------------------------------------------
__global__ void __launch_bounds__(TPB) feat_kernel(const float* __restrict__ prices)
{
    __shared__ float sI[S_ + (S_ >> 4)];   // padded inclusive prefix sums
    __shared__ float s_scan[16];
    __shared__ float s_red[16];
    __shared__ float s_plast, s_pm10;

    const int b    = blockIdx.x;
    const int t    = threadIdx.x;
    const int lane = t & 31;
    const int wid  = t >> 5;

    const float4* row4 =
        reinterpret_cast<const float4*>(prices + (size_t)b * S_) + t * (CHUNK / 4);

    // load 16 contiguous floats
    float p[CHUNK];
#pragma unroll
    for (int q = 0; q < CHUNK / 4; q++) {
        float4 v = row4[q];
        p[q * 4 + 0] = v.x; p[q * 4 + 1] = v.y;
        p[q * 4 + 2] = v.z; p[q * 4 + 3] = v.w;
    }

    // local inclusive scan + sum of squares
    float c[CHUNK];
    float p2 = p[0] * p[0];
    c[0] = p[0];
#pragma unroll
    for (int k = 1; k < CHUNK; k++) {
        c[k] = c[k - 1] + p[k];
        p2   = fmaf(p[k], p[k], p2);
    }
    const float tot = c[CHUNK - 1];

    // block-wide exclusive scan of per-thread totals (warp shuffles)
    float v = tot;
#pragma unroll
    for (int off = 1; off < 32; off <<= 1) {
        float n = __shfl_up_sync(0xffffffffu, v, off);
        if (lane >= off) v += n;
    }
    if (lane == 31) s_scan[wid] = v;
    if (t == TPB - 1) { s_plast = p[CHUNK - 1]; s_pm10 = p[CHUNK - 10]; } // i=4095, i=4086
    __syncthreads();
    if (wid == 0) {
        float w = (lane < 8) ? s_scan[lane] : 0.f;
#pragma unroll
        for (int off = 1; off < 8; off <<= 1) {
            float n = __shfl_up_sync(0xffffffffu, w, off);
            if (lane >= off) w += n;
        }
        if (lane < 8) s_scan[8 + lane] = w;
    }
    __syncthreads();
    const float base = ((wid > 0) ? s_scan[8 + wid - 1] : 0.f) + (v - tot);

    // write inclusive prefix (padded) to smem
#pragma unroll
    for (int k = 0; k < CHUNK; k++) sI[padi(t * CHUNK + k)] = base + c[k];
    __syncthreads();

    // trend: (p - sma20)/(sma20 + eps); sma20 = (I[i] - I[i-20]) / min(i+1,20)
    float tsum = 0.f;
    if (t >= 2) {
        // all i >= 32: full 20-window, rcnt = 0.05 (common path: 1 MUFU/elem)
#pragma unroll
        for (int k = 0; k < CHUNK; k++) {
            int   i  = t * CHUNK + k;
            float I  = base + c[k];
            float Ip = sI[padi(i - 20)];
            float sma = (I - Ip) * 0.05f;
            tsum += __fdividef(p[k] - sma, sma + EPS_);
        }
    } else {
        // threads 0,1 handle the clamped-window start
#pragma unroll
        for (int k = 0; k < CHUNK; k++) {
            int   i  = t * CHUNK + k;
            float I  = base + c[k];
            float Ip = (i >= 20) ? sI[padi(i - 20)] : 0.f;
            float cnt = (i >= 20) ? 20.f : (float)(i + 1);
            float sma = __fdividef(I - Ip, cnt);
            tsum += __fdividef(p[k] - sma, sma + EPS_);
        }
    }

    // block reduce tsum, p2
#pragma unroll
    for (int off = 16; off > 0; off >>= 1) {
        tsum += __shfl_xor_sync(0xffffffffu, tsum, off);
        p2   += __shfl_xor_sync(0xffffffffu, p2,   off);
    }
    if (lane == 0) { s_red[wid] = tsum; s_red[8 + wid] = p2; }
    __syncthreads();

    if (t == 0) {
        float T = 0.f, P2 = 0.f;
#pragma unroll
        for (int i = 0; i < 8; i++) { T += s_red[i]; P2 += s_red[8 + i]; }
        float psum  = sI[padi(S_ - 1)];
        float mean  = psum * (1.0f / S_);
        float f_trend = T * (1.0f / S_);
        float pl = s_plast, pm10 = s_pm10;
        float f_mom = (pl - pm10) / (pm10 + EPS_);
        float f_mr  = (pl - mean) / (mean + EPS_);
        float var   = (P2 - (float)S_ * mean * mean) * (1.0f / (float)(S_ - 1));
        float f_cyc = sqrtf(fmaxf(var, 0.f)) / (mean + EPS_);
        float4 cmb  = make_float4(f_trend, f_mom, f_mr, f_cyc);
        *reinterpret_cast<float4*>(&g_combined[b * 4]) = cmb;
    }
}

// ---------------------------------------------------------------------------
// Kernel B (v2): 16 rows per block-tile, all phases batched between barriers.
// head_w1 register-resident (amortized over 16 rows).
// ---------------------------------------------------------------------------
#define RPB 16                      // rows per block
#define MLP_GRID (B_ / RPB)         // 512

__global__ void __launch_bounds__(TPB) mlp_kernel(
    const float* __restrict__ enc_w,  const float* __restrict__ enc_b,
    const float* __restrict__ enc_g,  const float* __restrict__ enc_beta,
    const float* __restrict__ W1,     const float* __restrict__ b1,
    const float* __restrict__ W2,     const float* __restrict__ b2,
    float* __restrict__ rf_out, float* __restrict__ probs_out)
{
    __shared__ float s_cmb[RPB * 4];           // combined features for tile
    __shared__ float s_rf[RPB][256];           // layernormed features
    __shared__ float s_part[RPB][256];         // GEMM1 partials (per quarter)
    __shared__ float s_h[RPB][65];             // hidden (padded: stride 65)
    __shared__ float s_sum[RPB][8];            // LN partial sums per (row, warp)
    __shared__ float s_sq[RPB][8];
    __shared__ float s_b1[64], s_W2[256], s_b2[4];

    const int t    = threadIdx.x;
    const int lane = t & 31, wid = t >> 5;
    const int q = t >> 6;   // encoder index / quarter of head_w1 rows
    const int k = t & 63;   // column within 64
    const int r0 = blockIdx.x * RPB;

    // head_w1 slice in registers: w[jj] = W1[(q*64+jj)][k]
    float w[64];
#pragma unroll
    for (int jj = 0; jj < 64; jj++) w[jj] = W1[(q * 64 + jj) * 64 + k];

    const float ew0 = enc_w[q * 256 + 0 * 64 + k];
    const float ew1 = enc_w[q * 256 + 1 * 64 + k];
    const float ew2 = enc_w[q * 256 + 2 * 64 + k];
    const float ew3 = enc_w[q * 256 + 3 * 64 + k];
    const float eb  = enc_b[q * 64 + k];
    const float gg  = enc_g[q * 64 + k];
    const float bb  = enc_beta[q * 64 + k];

    if (t < 64) s_b1[t] = b1[t];
    s_W2[t] = W2[t];
    if (t < 4) s_b2[t] = b2[t];
    if (t < RPB * 4) s_cmb[t] = g_combined[r0 * 4 + t];
    __syncthreads();

    // ---- phase 1: encoder pre-activation + relu for all 16 rows ----
    float x[RPB];
#pragma unroll
    for (int r = 0; r < RPB; r++) {
        float pre = eb;
        pre = fmaf(ew0, s_cmb[r * 4 + 0], pre);
        pre = fmaf(ew1, s_cmb[r * 4 + 1], pre);
        pre = fmaf(ew2, s_cmb[r * 4 + 2], pre);
        pre = fmaf(ew3, s_cmb[r * 4 + 3], pre);
        x[r] = fmaxf(pre, 0.f);
    }

    // ---- phase 2: LN reductions (warp shuffles, all rows) ----
#pragma unroll
    for (int r = 0; r < RPB; r++) {
        float s = x[r], s2 = x[r] * x[r];
#pragma unroll
        for (int off = 16; off > 0; off >>= 1) {
            s  += __shfl_xor_sync(0xffffffffu, s,  off);
            s2 += __shfl_xor_sync(0xffffffffu, s2, off);
        }
        if (lane == 0) { s_sum[r][wid] = s; s_sq[r][wid] = s2; }
    }
    __syncthreads();

    const int gw = q * 2;
#pragma unroll
    for (int r = 0; r < RPB; r++) {
        float gs   = s_sum[r][gw] + s_sum[r][gw + 1];
        float gs2  = s_sq[r][gw]  + s_sq[r][gw + 1];
        float mu   = gs * (1.f / 64.f);
        float varr = gs2 * (1.f / 64.f) - mu * mu;
        float y = (x[r] - mu) * rsqrtf(varr + LNEPS_) * gg + bb;
        s_rf[r][t] = y;
        rf_out[(size_t)(r0 + r) * 256 + t] = y;   // coalesced per row
    }
    __syncthreads();

    // ---- phase 3: GEMM1 partials — 16 rows x 64-length dot per thread ----
#pragma unroll
    for (int r = 0; r < RPB; r++) {
        const float4* rf4 = reinterpret_cast<const float4*>(&s_rf[r][q * 64]);
        float a0 = 0.f, a1 = 0.f, a2 = 0.f, a3 = 0.f;
#pragma unroll
        for (int jj = 0; jj < 16; jj++) {
            float4 rv = rf4[jj];            // warp-broadcast (conflict-free)
            a0 = fmaf(w[jj * 4 + 0], rv.x, a0);
            a1 = fmaf(w[jj * 4 + 1], rv.y, a1);
            a2 = fmaf(w[jj * 4 + 2], rv.z, a2);
            a3 = fmaf(w[jj * 4 + 3], rv.w, a3);
        }
        s_part[r][t] = (a0 + a1) + (a2 + a3);
    }
    __syncthreads();

    // ---- phase 4: combine quarters, bias, relu -> s_h ----
#pragma unroll
    for (int i = 0; i < RPB * 64 / TPB; i++) {       // 4 iterations
        int idx = t + i * TPB;
        int r   = idx >> 6;
        int kk  = idx & 63;
        float h = s_b1[kk] + s_part[r][kk] + s_part[r][64 + kk]
                           + s_part[r][128 + kk] + s_part[r][192 + kk];
        s_h[r][kk] = fmaxf(h, 0.f);
    }
    __syncthreads();

    // ---- phase 5: logits + softmax (64 threads: one per (row, class)) ----
    if (t < RPB * 4) {
        int r = t >> 2, c = t & 3;
        float l = s_b2[c];
#pragma unroll
        for (int kk = 0; kk < 64; kk++)
            l = fmaf(s_h[r][kk], s_W2[kk * 4 + c], l);   // stride-65 rows: conflict-free

        float m = l;
        m = fmaxf(m, __shfl_xor_sync(0xffffffffu, m, 1));
        m = fmaxf(m, __shfl_xor_sync(0xffffffffu, m, 2));
        float e = __expf(l - m);
        float den = e;
        den += __shfl_xor_sync(0xffffffffu, den, 1);
        den += __shfl_xor_sync(0xffffffffu, den, 2);
        probs_out[(size_t)(r0 + r) * 4 + c] = __fdividef(e, den);
    }
}

// ---------------------------------------------------------------------------
extern "C" void kernel_launch(void* const* d_in, const int* in_sizes, int n_in,
                              void* d_out, int out_size)
{
    const float* prices   = (const float*)d_in[0];  // (8192, 4096, 1)
    const float* enc_w    = (const float*)d_in[1];  // (4, 4, 64)
    const float* enc_b    = (const float*)d_in[2];  // (4, 64)
    const float* enc_g    = (const float*)d_in[3];  // (4, 64)
    const float* enc_beta = (const float*)d_in[4];  // (4, 64)
    const float* head_w1  = (const float*)d_in[5];  // (256, 64)
    const float* head_b1  = (const float*)d_in[6];  // (64,)
    const float* head_w2  = (const float*)d_in[7];  // (64, 4)
    const float* head_b2  = (const float*)d_in[8];  // (4,)

    float* out       = (float*)d_out;
    float* rf_out    = out;                      // 8192*256
    float* probs_out = out + (size_t)B_ * 256;   // 8192*4

    feat_kernel<<<B_, TPB>>>(prices);
    mlp_kernel<<<MLP_GRID, TPB>>>(enc_w, enc_b, enc_g, enc_beta,
                                  head_w1, head_b1, head_w2, head_b2,
                                  rf_out, probs_out);
}